// round 2
// baseline (speedup 1.0000x reference)
#include <cuda_runtime.h>
#include <cuda_bf16.h>

#define FULL 0xffffffffu

static constexpr int B = 64;
static constexpr int S = 512;
static constexpr int H = 768;
static constexpr int L = 9;

// Scratch (no allocations allowed): emissions + per-batch partials
__device__ float g_em[B * S * L];     // [b][t][j]
__device__ float g_score[B];
__device__ float g_logZ[B];
__device__ float g_corr[B];

// ---------------------------------------------------------------------------
// Kernel 1: emissions = hidden @ W + b    (HBM/FMA-bound, stream hidden once)
// block = 256 threads (8 warps), each warp computes 8 rows; grid = 512
// ---------------------------------------------------------------------------
__global__ void __launch_bounds__(256) emis_kernel(const float* __restrict__ hidden,
                                                   const float* __restrict__ W,
                                                   const float* __restrict__ bias) {
    __shared__ float sW[H * L];  // 27648 B
    for (int i = threadIdx.x; i < H * L; i += blockDim.x) sW[i] = W[i];
    __syncthreads();

    int warp = threadIdx.x >> 5;
    int lane = threadIdx.x & 31;
    long row0 = (long)(blockIdx.x * 8 + warp) * 8;   // 8 rows per warp
    const float* h0 = hidden + row0 * H;

    float acc[8][9];
#pragma unroll
    for (int r = 0; r < 8; r++)
#pragma unroll
        for (int j = 0; j < 9; j++) acc[r][j] = 0.f;

#pragma unroll 2
    for (int k = 0; k < H / 32; k++) {
        int h = k * 32 + lane;
        float x[8];
#pragma unroll
        for (int r = 0; r < 8; r++) x[r] = h0[(long)r * H + h];
        float w[9];
#pragma unroll
        for (int j = 0; j < 9; j++) w[j] = sW[h * 9 + j];  // 9*lane mod 32: conflict-free
#pragma unroll
        for (int r = 0; r < 8; r++)
#pragma unroll
            for (int j = 0; j < 9; j++) acc[r][j] = fmaf(x[r], w[j], acc[r][j]);
    }

    // butterfly reduce each accumulator across the warp
#pragma unroll
    for (int r = 0; r < 8; r++)
#pragma unroll
        for (int j = 0; j < 9; j++) {
#pragma unroll
            for (int o = 16; o > 0; o >>= 1)
                acc[r][j] += __shfl_xor_sync(FULL, acc[r][j], o);
        }

    if (lane == 0) {
        float bb[9];
#pragma unroll
        for (int j = 0; j < 9; j++) bb[j] = bias[j];
        // 72 contiguous floats, 16B-aligned (row0 multiple of 8 -> 288B mult)
        float4* dst = (float4*)(g_em + row0 * 9);
        float v[72];
#pragma unroll
        for (int r = 0; r < 8; r++)
#pragma unroll
            for (int j = 0; j < 9; j++) v[r * 9 + j] = acc[r][j] + bb[j];
#pragma unroll
        for (int q = 0; q < 18; q++)
            dst[q] = make_float4(v[q * 4], v[q * 4 + 1], v[q * 4 + 2], v[q * 4 + 3]);
    }
}

// ---------------------------------------------------------------------------
// Kernel 2: mega-kernel, 192 blocks x 32 threads
//   blocks   0.. 63 : forward DP (logZ) in normal space  [latency-bound]
//   blocks  64..127 : Viterbi forward + backtrace + predict + correct
//   blocks 128..191 : gold-path score (numerator) + label_flat copy
// ---------------------------------------------------------------------------
__global__ void crf_kernel(const int* __restrict__ label,
                           const int* __restrict__ mask,
                           const float* __restrict__ startT,
                           const float* __restrict__ endT,
                           const float* __restrict__ trans,
                           float* __restrict__ out) {
    __shared__ unsigned char bp[(S - 1) * L];  // Viterbi backpointers (4599 B)

    int blk = blockIdx.x;
    int lane = threadIdx.x;
    int jj = lane % 9;

    if (blk < 64) {
        // ------- forward algorithm (logZ), normal space with renorm -------
        int b = blk;
        const float* emb = g_em + (long)b * S * L;
        const int* mb = mask + b * S;

        float E[9];   // E[i] = exp(T[i][jj])
#pragma unroll
        for (int i = 0; i < 9; i++) E[i] = __expf(trans[i * 9 + jj]);
        float eendexp = __expf(endT[jj]);

        float p = __expf(startT[jj] + emb[jj]);  // t = 0, magnitude ~1
        float logacc = 0.f;

        // two-stage prefetch rings: raw LDG (depth 8) -> exp (distance 4)
        float rbuf[8], ebuf[8];
        int mbufv[8];
#pragma unroll
        for (int t = 1; t <= 8; t++) {
            rbuf[(t - 1) & 7] = emb[t * 9 + jj];
            mbufv[(t - 1) & 7] = mb[t];
        }
#pragma unroll
        for (int t = 1; t <= 4; t++) ebuf[(t - 1) & 7] = __expf(rbuf[(t - 1) & 7]);

        for (int t = 1; t < S; t++) {
            int s0 = (t - 1) & 7;
            float w = ebuf[s0];
            int mt = mbufv[s0];

            // stage: exp for time t+4 (raw loaded >= 4 iters ago)
            if (t + 4 < S) {
                int s4 = (t + 3) & 7;
                ebuf[s4] = __expf(rbuf[s4]);
            }
            // stage: raw load for time t+8
            if (t + 8 < S) {
                rbuf[s0] = emb[(t + 8) * 9 + jj];
                mbufv[s0] = mb[t + 8];
            }

            float pi[9];
#pragma unroll
            for (int i = 0; i < 9; i++) pi[i] = __shfl_sync(FULL, p, i);
            float m0 = pi[0] * E[0], m1 = pi[1] * E[1], m2 = pi[2] * E[2];
            float m3 = pi[3] * E[3], m4 = pi[4] * E[4], m5 = pi[5] * E[5];
            float m6 = pi[6] * E[6], m7 = pi[7] * E[7], m8 = pi[8] * E[8];
            float s = (((m0 + m1) + (m2 + m3)) + ((m4 + m5) + (m6 + m7))) + m8;
            float pn = s * w;
            p = (mt > 0) ? pn : p;

            if ((t & 15) == 0) {
                float r = __shfl_sync(FULL, p, 0);
                float inv = __fdividef(1.0f, r);
                p *= inv;
                logacc += __logf(r);
            }
        }
        float f = p * eendexp;
        float tot = 0.f;
#pragma unroll
        for (int i = 0; i < 9; i++) tot += __shfl_sync(FULL, f, i);
        if (lane == 0) g_logZ[b] = logacc + __logf(tot);

    } else if (blk < 128) {
        // ------------------- Viterbi decode (bit-exact) -------------------
        int b = blk - 64;
        const float* emb = g_em + (long)b * S * L;
        float Tc[9];
#pragma unroll
        for (int i = 0; i < 9; i++) Tc[i] = trans[i * 9 + jj];
        float v = startT[jj] + emb[jj];

        float ebuf[8];
#pragma unroll
        for (int t = 1; t <= 8; t++) ebuf[(t - 1) & 7] = emb[t * 9 + jj];

        for (int t = 1; t < S; t++) {
            int s0 = (t - 1) & 7;
            float e = ebuf[s0];
            if (t + 8 < S) ebuf[s0] = emb[(t + 8) * 9 + jj];

            float vi[9];
#pragma unroll
            for (int i = 0; i < 9; i++)
                vi[i] = (__shfl_sync(FULL, v, i) + Tc[i]) + e;  // ref op order
            // exact tree max (max is rounding-free)
            float a01 = fmaxf(vi[0], vi[1]);
            float a23 = fmaxf(vi[2], vi[3]);
            float a45 = fmaxf(vi[4], vi[5]);
            float a67 = fmaxf(vi[6], vi[7]);
            float a03 = fmaxf(a01, a23);
            float a47 = fmaxf(a45, a67);
            float M = fmaxf(fmaxf(a03, a47), vi[8]);
            // first-occurrence argmax, off the value chain
            int arg = 8;
#pragma unroll
            for (int i = 7; i >= 0; i--) arg = (vi[i] == M) ? i : arg;
            if (lane < 9) bp[(t - 1) * 9 + jj] = (unsigned char)arg;
            v = M;
        }
        __syncwarp();

        float fj = v + endT[jj];
        float fv[9];
#pragma unroll
        for (int i = 0; i < 9; i++) fv[i] = __shfl_sync(FULL, fj, i);

        if (lane == 0) {
            float best = fv[0];
            int tag = 0;
#pragma unroll
            for (int i = 1; i < 9; i++)
                if (fv[i] > best) { best = fv[i]; tag = i; }   // first-max tie
            const int* lb = label + b * S;
            float* pout = out + 2 + (long)b * S;
            float cnt = 0.f;
            {
                int lab = lb[S - 1];
                int pv = (lab > 0) ? tag : 0;
                pout[S - 1] = (float)pv;
                cnt += (pv == lab) ? 1.f : 0.f;
            }
            for (int t = S - 2; t >= 0; t--) {
                tag = bp[t * 9 + tag];
                int lab = lb[t];
                int pv = (lab > 0) ? tag : 0;
                pout[t] = (float)pv;
                cnt += (pv == lab) ? 1.f : 0.f;
            }
            g_corr[b] = cnt;
        }

    } else {
        // --------- gold path score (masked scan) + label copy ---------
        int b = blk - 128;
        const int* lb = label + b * S;
        const int* mb = mask + b * S;
        const float* emb = g_em + (long)b * S * L;
        int t0 = lane * 16;

        int ll = -1;
#pragma unroll
        for (int k = 0; k < 16; k++) {
            int t = t0 + k;
            if ((t == 0) | (mb[t] > 0)) ll = t;
        }
        int inc = ll;
#pragma unroll
        for (int o = 1; o < 32; o <<= 1) {
            int vv = __shfl_up_sync(FULL, inc, o);
            if (lane >= o) inc = max(inc, vv);
        }
        int exc = __shfl_up_sync(FULL, inc, 1);
        if (lane == 0) exc = -1;
        int lastAll = __shfl_sync(FULL, inc, 31);

        float sc = 0.f;
        int prevIdx = exc;
#pragma unroll
        for (int k = 0; k < 16; k++) {
            int t = t0 + k;
            int mt = mb[t];
            int tg = lb[t];
            if (t >= 1) {
                int pt = lb[prevIdx];
                float s = trans[pt * 9 + tg] + emb[t * 9 + tg];
                sc += s * (float)mt;
            }
            if ((t == 0) | (mt > 0)) prevIdx = t;
        }
#pragma unroll
        for (int o = 16; o > 0; o >>= 1) sc += __shfl_xor_sync(FULL, sc, o);

        if (lane == 0) {
            int tg0 = lb[0];
            g_score[b] = startT[tg0] + emb[tg0] + sc + endT[lb[lastAll]];
        }

        float* lout = out + 2 + (long)B * S;
        for (int t = lane; t < S; t += 32)
            lout[(long)b * S + t] = (float)lb[t];
    }
}

// ---------------------------------------------------------------------------
// Kernel 3: finalize loss & correct
// ---------------------------------------------------------------------------
__global__ void fin_kernel(float* __restrict__ out) {
    __shared__ float sd[64], sc[64];
    int i = threadIdx.x;
    sd[i] = g_score[i] - g_logZ[i];
    sc[i] = g_corr[i];
    __syncthreads();
    if (i == 0) {
        float s = 0.f, c = 0.f;
        for (int k = 0; k < 64; k++) { s += sd[k]; c += sc[k]; }
        out[0] = -s / (float)B;
        out[1] = c;
    }
}

// ---------------------------------------------------------------------------
extern "C" void kernel_launch(void* const* d_in, const int* in_sizes, int n_in,
                              void* d_out, int out_size) {
    const float* hidden = (const float*)d_in[0];
    const int*   label  = (const int*)d_in[1];
    const int*   mask   = (const int*)d_in[2];
    const float* W      = (const float*)d_in[3];
    const float* bias   = (const float*)d_in[4];
    const float* startT = (const float*)d_in[5];
    const float* endT   = (const float*)d_in[6];
    const float* trans  = (const float*)d_in[7];
    float* out = (float*)d_out;

    emis_kernel<<<512, 256>>>(hidden, W, bias);
    crf_kernel<<<192, 32>>>(label, mask, startT, endT, trans, out);
    fin_kernel<<<1, 64>>>(out);
}

// round 3
// speedup vs baseline: 2.0520x; 2.0520x over previous
#include <cuda_runtime.h>
#include <cuda_bf16.h>

#define FULL 0xffffffffu

static constexpr int B = 64;
static constexpr int S = 512;
static constexpr int H = 768;
static constexpr int L = 9;

__device__ float g_em[B * S * L];     // [b][t][j]
__device__ float g_score[B];
__device__ float g_logZ[B];
__device__ float g_corr[B];

// ---------------------------------------------------------------------------
// Kernel 1: emissions = hidden @ W + b
// block 256 (8 warps), 2 rows per warp, float4 loads; grid = 2048
// W staged transposed [9][768] in smem -> conflict-free LDS.128 per j
// ---------------------------------------------------------------------------
__global__ void __launch_bounds__(256) emis_kernel(const float* __restrict__ hidden,
                                                   const float* __restrict__ W,
                                                   const float* __restrict__ bias) {
    __shared__ float sWT[L * H];  // [j][h], 27648 B
    for (int i = threadIdx.x; i < L * H; i += 256) {
        int j = i / H, h = i - j * H;
        sWT[i] = W[h * L + j];
    }
    __syncthreads();

    int warp = threadIdx.x >> 5;
    int lane = threadIdx.x & 31;
    long row0 = (long)(blockIdx.x * 8 + warp) * 2;
    const float* h0 = hidden + row0 * H;

    float acc0[9], acc1[9];
#pragma unroll
    for (int j = 0; j < 9; j++) { acc0[j] = 0.f; acc1[j] = 0.f; }

#pragma unroll
    for (int k = 0; k < 6; k++) {
        int hb = k * 128 + lane * 4;
        float4 x0 = *(const float4*)(h0 + hb);
        float4 x1 = *(const float4*)(h0 + H + hb);
#pragma unroll
        for (int j = 0; j < 9; j++) {
            float4 w4 = *(const float4*)(sWT + j * H + hb);
            acc0[j] = fmaf(x0.x, w4.x, acc0[j]);
            acc0[j] = fmaf(x0.y, w4.y, acc0[j]);
            acc0[j] = fmaf(x0.z, w4.z, acc0[j]);
            acc0[j] = fmaf(x0.w, w4.w, acc0[j]);
            acc1[j] = fmaf(x1.x, w4.x, acc1[j]);
            acc1[j] = fmaf(x1.y, w4.y, acc1[j]);
            acc1[j] = fmaf(x1.z, w4.z, acc1[j]);
            acc1[j] = fmaf(x1.w, w4.w, acc1[j]);
        }
    }

    // butterfly reduce 18 accumulators across the warp
#pragma unroll
    for (int j = 0; j < 9; j++) {
#pragma unroll
        for (int o = 16; o > 0; o >>= 1) {
            acc0[j] += __shfl_xor_sync(FULL, acc0[j], o);
            acc1[j] += __shfl_xor_sync(FULL, acc1[j], o);
        }
    }

    if (lane == 0) {
        float v[18];
#pragma unroll
        for (int j = 0; j < 9; j++) {
            float bb = bias[j];
            v[j] = acc0[j] + bb;
            v[9 + j] = acc1[j] + bb;
        }
        float2* dst = (float2*)(g_em + row0 * 9);  // row0 even -> 8B aligned
#pragma unroll
        for (int q = 0; q < 9; q++) dst[q] = make_float2(v[2 * q], v[2 * q + 1]);
    }
}

// ---------------------------------------------------------------------------
// Kernel 2: 192 blocks x 32 threads
//   blocks   0.. 63 : forward DP (logZ), normal space, blocked prefetch
//   blocks  64..127 : Viterbi forward + backtrace + predict + correct
//   blocks 128..191 : gold-path score + label_flat copy
// ---------------------------------------------------------------------------
__global__ void crf_kernel(const int* __restrict__ label,
                           const int* __restrict__ mask,
                           const float* __restrict__ startT,
                           const float* __restrict__ endT,
                           const float* __restrict__ trans,
                           float* __restrict__ out) {
    __shared__ unsigned char bp[(S - 1) * L];  // Viterbi backpointers

    int blk = blockIdx.x;
    int lane = threadIdx.x;
    int jj = lane % 9;

    if (blk < 64) {
        // ---------- forward algorithm (logZ), normal space ----------
        int b = blk;
        const float* emb = g_em + (long)b * S * L;
        const int* mb = mask + b * S;

        float E[9];
#pragma unroll
        for (int i = 0; i < 9; i++) E[i] = __expf(trans[i * 9 + jj]);
        float eend = __expf(endT[jj]);

        float p = __expf(startT[jj] + emb[jj]);
        float logacc = 0.f;

        float cur[8]; int mcur[8];
#pragma unroll
        for (int k = 0; k < 8; k++) { cur[k] = emb[(1 + k) * 9 + jj]; mcur[k] = mb[1 + k]; }

        int tb = 1;
        for (; tb + 8 <= S; tb += 8) {
            float w[8];
#pragma unroll
            for (int k = 0; k < 8; k++) w[k] = __expf(cur[k]);   // off-chain, batched
            float nxt[8]; int mnxt[8];
#pragma unroll
            for (int k = 0; k < 8; k++) {                         // prefetch next block
                int t2 = tb + 8 + k;
                if (t2 < S) { nxt[k] = emb[t2 * 9 + jj]; mnxt[k] = mb[t2]; }
                else        { nxt[k] = 0.f;              mnxt[k] = 0; }
            }
#pragma unroll
            for (int k = 0; k < 8; k++) {                         // 8 chain steps
                float p0 = __shfl_sync(FULL, p, 0), p1 = __shfl_sync(FULL, p, 1);
                float p2 = __shfl_sync(FULL, p, 2), p3 = __shfl_sync(FULL, p, 3);
                float p4 = __shfl_sync(FULL, p, 4), p5 = __shfl_sync(FULL, p, 5);
                float p6 = __shfl_sync(FULL, p, 6), p7 = __shfl_sync(FULL, p, 7);
                float p8 = __shfl_sync(FULL, p, 8);
                float s01 = fmaf(p0, E[0], p1 * E[1]);
                float s23 = fmaf(p2, E[2], p3 * E[3]);
                float s45 = fmaf(p4, E[4], p5 * E[5]);
                float s67 = fmaf(p6, E[6], p7 * E[7]);
                float s = ((s01 + s23) + (s45 + s67)) + p8 * E[8];
                float pn = s * w[k];
                p = (mcur[k] > 0) ? pn : p;
                int t = tb + k;
                if ((t & 15) == 0) {                              // renorm
                    float r = __shfl_sync(FULL, p, 0);
                    logacc += __logf(r);
                    p *= __fdividef(1.0f, r);
                }
            }
#pragma unroll
            for (int k = 0; k < 8; k++) { cur[k] = nxt[k]; mcur[k] = mnxt[k]; }
        }
        // tail: t = 505..511 (7 steps), held in cur[0..6]
#pragma unroll
        for (int k = 0; k < 7; k++) {
            float w = __expf(cur[k]);
            float p0 = __shfl_sync(FULL, p, 0), p1 = __shfl_sync(FULL, p, 1);
            float p2 = __shfl_sync(FULL, p, 2), p3 = __shfl_sync(FULL, p, 3);
            float p4 = __shfl_sync(FULL, p, 4), p5 = __shfl_sync(FULL, p, 5);
            float p6 = __shfl_sync(FULL, p, 6), p7 = __shfl_sync(FULL, p, 7);
            float p8 = __shfl_sync(FULL, p, 8);
            float s01 = fmaf(p0, E[0], p1 * E[1]);
            float s23 = fmaf(p2, E[2], p3 * E[3]);
            float s45 = fmaf(p4, E[4], p5 * E[5]);
            float s67 = fmaf(p6, E[6], p7 * E[7]);
            float s = ((s01 + s23) + (s45 + s67)) + p8 * E[8];
            float pn = s * w;
            p = (mcur[k] > 0) ? pn : p;
        }

        float f = p * eend;
        float tot = 0.f;
#pragma unroll
        for (int i = 0; i < 9; i++) tot += __shfl_sync(FULL, f, i);
        if (lane == 0) g_logZ[b] = logacc + __logf(tot);

    } else if (blk < 128) {
        // ---------- Viterbi decode (bit-exact path scoring) ----------
        int b = blk - 64;
        const float* emb = g_em + (long)b * S * L;
        float Tc[9];
#pragma unroll
        for (int i = 0; i < 9; i++) Tc[i] = trans[i * 9 + jj];
        float v = startT[jj] + emb[jj];

        float cur[8];
#pragma unroll
        for (int k = 0; k < 8; k++) cur[k] = emb[(1 + k) * 9 + jj];

        int tb = 1;
        for (; tb + 8 <= S; tb += 8) {
            float nxt[8];
#pragma unroll
            for (int k = 0; k < 8; k++) {
                int t2 = tb + 8 + k;
                nxt[k] = (t2 < S) ? emb[t2 * 9 + jj] : 0.f;
            }
#pragma unroll
            for (int k = 0; k < 8; k++) {
                float e = cur[k];
                float vi[9];
#pragma unroll
                for (int i = 0; i < 9; i++)
                    vi[i] = (__shfl_sync(FULL, v, i) + Tc[i]) + e;  // ref op order
                float a01 = fmaxf(vi[0], vi[1]);
                float a23 = fmaxf(vi[2], vi[3]);
                float a45 = fmaxf(vi[4], vi[5]);
                float a67 = fmaxf(vi[6], vi[7]);
                float M = fmaxf(fmaxf(fmaxf(a01, a23), fmaxf(a45, a67)), vi[8]);
                int arg = 8;                                        // first-occurrence argmax
#pragma unroll
                for (int i = 7; i >= 0; i--) arg = (vi[i] == M) ? i : arg;
                if (lane < 9) bp[(tb + k - 1) * 9 + jj] = (unsigned char)arg;
                v = M;
            }
#pragma unroll
            for (int k = 0; k < 8; k++) cur[k] = nxt[k];
        }
#pragma unroll
        for (int k = 0; k < 7; k++) {                               // t = 505..511
            float e = cur[k];
            float vi[9];
#pragma unroll
            for (int i = 0; i < 9; i++)
                vi[i] = (__shfl_sync(FULL, v, i) + Tc[i]) + e;
            float a01 = fmaxf(vi[0], vi[1]);
            float a23 = fmaxf(vi[2], vi[3]);
            float a45 = fmaxf(vi[4], vi[5]);
            float a67 = fmaxf(vi[6], vi[7]);
            float M = fmaxf(fmaxf(fmaxf(a01, a23), fmaxf(a45, a67)), vi[8]);
            int arg = 8;
#pragma unroll
            for (int i = 7; i >= 0; i--) arg = (vi[i] == M) ? i : arg;
            if (lane < 9) bp[(tb + k - 1) * 9 + jj] = (unsigned char)arg;
            v = M;
        }
        __syncwarp();

        float fj = v + endT[jj];
        float fv[9];
#pragma unroll
        for (int i = 0; i < 9; i++) fv[i] = __shfl_sync(FULL, fj, i);

        if (lane == 0) {
            float best = fv[0];
            int tag = 0;
#pragma unroll
            for (int i = 1; i < 9; i++)
                if (fv[i] > best) { best = fv[i]; tag = i; }
            const int* lb = label + b * S;
            float* pout = out + 2 + (long)b * S;
            float cnt = 0.f;
            {
                int lab = lb[S - 1];
                int pv = (lab > 0) ? tag : 0;
                pout[S - 1] = (float)pv;
                cnt += (pv == lab) ? 1.f : 0.f;
            }
            for (int t = S - 2; t >= 0; t--) {
                tag = bp[t * 9 + tag];
                int lab = lb[t];
                int pv = (lab > 0) ? tag : 0;
                pout[t] = (float)pv;
                cnt += (pv == lab) ? 1.f : 0.f;
            }
            g_corr[b] = cnt;
        }

    } else {
        // ---------- gold path score (masked scan) + label copy ----------
        int b = blk - 128;
        const int* lb = label + b * S;
        const int* mb = mask + b * S;
        const float* emb = g_em + (long)b * S * L;
        int t0 = lane * 16;

        int ll = -1;
#pragma unroll
        for (int k = 0; k < 16; k++) {
            int t = t0 + k;
            if ((t == 0) | (mb[t] > 0)) ll = t;
        }
        int inc = ll;
#pragma unroll
        for (int o = 1; o < 32; o <<= 1) {
            int vv = __shfl_up_sync(FULL, inc, o);
            if (lane >= o) inc = max(inc, vv);
        }
        int exc = __shfl_up_sync(FULL, inc, 1);
        if (lane == 0) exc = -1;
        int lastAll = __shfl_sync(FULL, inc, 31);

        float sc = 0.f;
        int prevIdx = exc;
#pragma unroll
        for (int k = 0; k < 16; k++) {
            int t = t0 + k;
            int mt = mb[t];
            int tg = lb[t];
            if (t >= 1) {
                int pt = lb[prevIdx];
                float s = trans[pt * 9 + tg] + emb[t * 9 + tg];
                sc += s * (float)mt;
            }
            if ((t == 0) | (mt > 0)) prevIdx = t;
        }
#pragma unroll
        for (int o = 16; o > 0; o >>= 1) sc += __shfl_xor_sync(FULL, sc, o);

        if (lane == 0) {
            int tg0 = lb[0];
            g_score[b] = startT[tg0] + emb[tg0] + sc + endT[lb[lastAll]];
        }

        float* lout = out + 2 + (long)B * S;
        for (int t = lane; t < S; t += 32)
            lout[(long)b * S + t] = (float)lb[t];
    }
}

// ---------------------------------------------------------------------------
__global__ void fin_kernel(float* __restrict__ out) {
    __shared__ float sd[64], sc[64];
    int i = threadIdx.x;
    sd[i] = g_score[i] - g_logZ[i];
    sc[i] = g_corr[i];
    __syncthreads();
    if (i == 0) {
        float s = 0.f, c = 0.f;
        for (int k = 0; k < 64; k++) { s += sd[k]; c += sc[k]; }
        out[0] = -s / (float)B;
        out[1] = c;
    }
}

// ---------------------------------------------------------------------------
extern "C" void kernel_launch(void* const* d_in, const int* in_sizes, int n_in,
                              void* d_out, int out_size) {
    const float* hidden = (const float*)d_in[0];
    const int*   label  = (const int*)d_in[1];
    const int*   mask   = (const int*)d_in[2];
    const float* W      = (const float*)d_in[3];
    const float* bias   = (const float*)d_in[4];
    const float* startT = (const float*)d_in[5];
    const float* endT   = (const float*)d_in[6];
    const float* trans  = (const float*)d_in[7];
    float* out = (float*)d_out;

    emis_kernel<<<2048, 256>>>(hidden, W, bias);
    crf_kernel<<<192, 32>>>(label, mask, startT, endT, trans, out);
    fin_kernel<<<1, 64>>>(out);
}